// round 1
// baseline (speedup 1.0000x reference)
#include <cuda_runtime.h>
#include <math.h>

// CBOW negative-sampling loss.
// Inputs (metadata order):
//   d_in[0]: in_embed  float32 [100000, 128]
//   d_in[1]: out_embed float32 [100000, 128]
//   d_in[2]: context   int32   [B, 8]
//   d_in[3]: target    int32   [B]
//   d_in[4]: negatives int32   [B, 10]
// Output: float32 [B]
//
// One warp per batch element. Lane l owns float4 chunk l of each 128-float row
// (32 lanes x 16B = 512B = one full row, perfectly coalesced).

#define CTX 8
#define NEG 10
#define D   128

__device__ __forceinline__ float log_sigmoid(float x) {
    // log(sigmoid(x)) = min(x,0) - log1p(exp(-|x|)), numerically stable
    return fminf(x, 0.0f) - log1pf(__expf(-fabsf(x)));
}

__global__ __launch_bounds__(256) void cbow_neg_kernel(
    const float* __restrict__ in_embed,
    const float* __restrict__ out_embed,
    const int*   __restrict__ context,
    const int*   __restrict__ target,
    const int*   __restrict__ negatives,
    float*       __restrict__ out,
    int B)
{
    const int warp = (blockIdx.x * blockDim.x + threadIdx.x) >> 5;
    const int lane = threadIdx.x & 31;
    if (warp >= B) return;

    // ---- v = mean of 8 context embeddings (this lane's float4 slice) ----
    float4 v = make_float4(0.f, 0.f, 0.f, 0.f);
    #pragma unroll
    for (int c = 0; c < CTX; c++) {
        const int idx = __ldg(&context[warp * CTX + c]);        // warp-uniform
        const float4 e = __ldg(reinterpret_cast<const float4*>(
                              in_embed + (size_t)idx * D) + lane);
        v.x += e.x; v.y += e.y; v.z += e.z; v.w += e.w;
    }
    const float inv = 1.0f / (float)CTX;
    v.x *= inv; v.y *= inv; v.z *= inv; v.w *= inv;

    // ---- 11 dot products: target + 10 negatives ----
    float s[NEG + 1];
    {
        const int t = __ldg(&target[warp]);
        const float4 u = __ldg(reinterpret_cast<const float4*>(
                              out_embed + (size_t)t * D) + lane);
        s[0] = v.x * u.x + v.y * u.y + v.z * u.z + v.w * u.w;
    }
    #pragma unroll
    for (int k = 0; k < NEG; k++) {
        const int n = __ldg(&negatives[warp * NEG + k]);        // warp-uniform
        const float4 u = __ldg(reinterpret_cast<const float4*>(
                              out_embed + (size_t)n * D) + lane);
        s[1 + k] = v.x * u.x + v.y * u.y + v.z * u.z + v.w * u.w;
    }

    // ---- butterfly reduce all 11 partial dots across the warp ----
    #pragma unroll
    for (int i = 0; i < NEG + 1; i++) {
        float x = s[i];
        x += __shfl_xor_sync(0xffffffffu, x, 16);
        x += __shfl_xor_sync(0xffffffffu, x, 8);
        x += __shfl_xor_sync(0xffffffffu, x, 4);
        x += __shfl_xor_sync(0xffffffffu, x, 2);
        x += __shfl_xor_sync(0xffffffffu, x, 1);
        s[i] = x;
    }

    // ---- loss = -(log_sigmoid(pos) + sum_k log_sigmoid(-neg_k)) ----
    if (lane == 0) {
        float loss = -log_sigmoid(s[0]);
        #pragma unroll
        for (int k = 0; k < NEG; k++)
            loss -= log_sigmoid(-s[1 + k]);
        out[warp] = loss;
    }
}

extern "C" void kernel_launch(void* const* d_in, const int* in_sizes, int n_in,
                              void* d_out, int out_size)
{
    const float* in_embed  = (const float*)d_in[0];
    const float* out_embed = (const float*)d_in[1];
    const int*   context   = (const int*)d_in[2];
    const int*   target    = (const int*)d_in[3];
    const int*   negatives = (const int*)d_in[4];
    float*       out       = (float*)d_out;

    const int B = out_size;                 // 16384
    const int threads = 256;                // 8 warps/block
    const int blocks  = (B * 32 + threads - 1) / threads;
    cbow_neg_kernel<<<blocks, threads>>>(in_embed, out_embed, context, target,
                                         negatives, out, B);
}